// round 9
// baseline (speedup 1.0000x reference)
#include <cuda_runtime.h>
#include <math.h>

// Problem constants (match reference)
#define T_STEPS 1024
#define B_SIZE  32768
#define G1      50
#define H1      32
#define G2      20
#define NBLOCKS 512
#define CH_T    128                    // scan steps per chunk
#define NCH     (T_STEPS / CH_T)       // 8 chunks
#define PROD_PER_CH 64                 // blocks producing each chunk's betas

// Device globals (zero-initialized at module load; reset by last-exiting block)
__device__ float g_cbeta[T_STEPS];
__device__ int   g_cdone[NCH];
__device__ int   g_exit;

// ---------------------------------------------------------------------------
// Fused pipelined kernel.
//  Phase 1: warp w of block b computes beta(2b + w) (factorized RBF layer 2,
//           warp-local), publishes, and bumps its chunk counter (b>>6).
//  Phase 2: the DRAM-write-bound Euler scan, consuming betas chunk-by-chunk;
//           each chunk waits only on its 64 producer blocks — dispatch skew
//           is absorbed by the pipeline instead of maxed by a grid barrier.
// Residency: 512 blocks x 64 thr, ~1.1KB smem, ~40 regs -> whole grid in one
// wave, so the flag spins cannot deadlock. The 512th block to finish resets
// all counters (every block has passed every wait by then); graph replays
// are stream-ordered, so each launch starts with clean flags.
// ---------------------------------------------------------------------------
__global__ void __launch_bounds__(64)
fused_kan_sir_kernel(const float* __restrict__ t_steps,
                     const float* __restrict__ initial_I,
                     const float* __restrict__ grid1,
                     const float* __restrict__ spline_w1, // [50,32]
                     const float* __restrict__ base_w1,   // [32]
                     const float* __restrict__ grid2,
                     const float* __restrict__ spline_w2, // [32,20]
                     const float* __restrict__ base_w2,   // [32]
                     const float* __restrict__ gamma_param,
                     float* __restrict__ out)
{
    __shared__ float sbasis[2][G1];     // per-warp layer-1 basis
    __shared__ float C2[G2];
    __shared__ float sc[CH_T + 2];      // current beta chunk (+prefetch pad)

    const int tid  = threadIdx.x;
    const int w    = tid >> 5;
    const int lane = tid & 31;

    // ---- Prefetch scan inputs (latency hides under phase 1) ----
    const int   b      = blockIdx.x * 64 + tid;
    const float I_init = initial_I[b];
    const float gp     = gamma_param[0];
    const float dt     = t_steps[1] - t_steps[0];

    // ---- Phase 1: beta(t), t = 2*bid + w, one warp per t ----
    {
        const int   t = blockIdx.x * 2 + w;
        const float x = t_steps[t];

        {   // layer-1 basis: 50 exps per warp
            float d = x - grid1[lane];
            sbasis[w][lane] = __expf(-10.0f * d * d);
            if (lane < G1 - 32) {
                float d2 = x - grid1[lane + 32];
                sbasis[w][lane + 32] = __expf(-10.0f * d2 * d2);
            }
        }
        if (lane < G2) {    // both warps write identical values — benign
            float v = grid2[lane] - 0.5f;
            C2[lane] = __expf(-10.0f * v * v);
        }
        __syncwarp();

        // h[lane] = x*base_w1 + sum_g basis[g]*w1[g][lane]
        float acc0 = x * base_w1[lane];
        float acc1 = 0.0f;
        #pragma unroll
        for (int g = 0; g < G1 - 1; g += 2) {
            acc0 = fmaf(sbasis[w][g],     spline_w1[g * H1 + lane],       acc0);
            acc1 = fmaf(sbasis[w][g + 1], spline_w1[(g + 1) * H1 + lane], acc1);
        }
        const float h = fmaf(sbasis[w][G1 - 1], spline_w1[(G1 - 1) * H1 + lane],
                             acc0 + acc1);

        // layer-2 factorized RBF (3 exps instead of 20)
        float u = fminf(fmaxf(h - 0.5f, -2.5f), 2.5f);  // clamp: basis ~0 there
        const float v0 = grid2[0] - 0.5f;
        const float dv = grid2[1] - grid2[0];
        const float e0 = __expf(-10.0f * u * u);
        float       tk = __expf(20.0f * u * v0);
        const float f  = __expf(20.0f * u * dv);

        float acc = 0.0f;
        #pragma unroll
        for (int k = 0; k < G2; k++) {
            acc = fmaf(tk * C2[k], spline_w2[lane * G2 + k], acc);
            tk *= f;
        }
        acc = fmaf(h, base_w2[lane], e0 * acc);

        #pragma unroll
        for (int o = 16; o > 0; o >>= 1)
            acc += __shfl_down_sync(0xFFFFFFFFu, acc, o);

        if (lane == 0) {
            float beta = fmaxf(acc, 0.0f) + log1pf(expf(-fabsf(acc))); // accurate
            g_cbeta[t] = dt * beta;
        }
    }
    __syncthreads();
    if (tid == 0) {
        __threadfence();                                   // publish g_cbeta
        atomicAdd(&g_cdone[blockIdx.x >> 6], 1);
    }

    // ---- Phase 2: chunked scan ----
    float I = I_init;
    float S = 1.0f - I;
    const float gamma = fmaxf(gp, 0.0f) + log1pf(expf(-fabsf(gp)));
    const float a     = 1.0f - dt * gamma;

    float* outp = out + b;

    #pragma unroll 1
    for (int c = 0; c < NCH; c++) {
        if (tid == 0) {
            while (*((volatile int*)&g_cdone[c]) < PROD_PER_CH) { }
        }
        __syncthreads();
        sc[tid]      = __ldcg(&g_cbeta[c * CH_T + tid]);
        sc[tid + 64] = __ldcg(&g_cbeta[c * CH_T + 64 + tid]);
        if (tid == 0) sc[CH_T] = 0.0f;                     // prefetch sentinel
        __syncthreads();

        float* op = outp + (size_t)c * CH_T * B_SIZE;
        float cb = sc[0];
        #pragma unroll 8
        for (int u = 0; u < CH_T; u++) {
            const float cbn = sc[u + 1];                   // prefetch next beta
            const float ni = cb * (S * I);                 // dt * new_infections
            I = fmaf(I, a, ni);                            // clips: state in [0,1]
            S = S - ni;
            op[(size_t)u * B_SIZE] = I;
            cb = cbn;
        }
        __syncthreads();                                   // sc reused next chunk
    }

    // ---- Reset flags for the next replay (last-exiting block) ----
    if (tid == 0) {
        int old = atomicAdd(&g_exit, 1);
        if (old == NBLOCKS - 1) {
            #pragma unroll
            for (int i = 0; i < NCH; i++) g_cdone[i] = 0;
            g_exit = 0;
            __threadfence();
        }
    }
}

// ---------------------------------------------------------------------------
// Inputs (metadata order):
// 0: t_steps [1024], 1: initial_I [32768], 2: grid1 [50], 3: spline_w1 [1600],
// 4: base_w1 [32], 5: grid2 [20], 6: spline_w2 [640], 7: base_w2 [32],
// 8: gamma_param [1]
// ---------------------------------------------------------------------------
extern "C" void kernel_launch(void* const* d_in, const int* in_sizes, int n_in,
                              void* d_out, int out_size)
{
    const float* t_steps    = (const float*)d_in[0];
    const float* initial_I  = (const float*)d_in[1];
    const float* grid1      = (const float*)d_in[2];
    const float* spline_w1  = (const float*)d_in[3];
    const float* base_w1    = (const float*)d_in[4];
    const float* grid2      = (const float*)d_in[5];
    const float* spline_w2  = (const float*)d_in[6];
    const float* base_w2    = (const float*)d_in[7];
    const float* gamma_p    = (const float*)d_in[8];
    float* out              = (float*)d_out;

    fused_kan_sir_kernel<<<NBLOCKS, 64>>>(t_steps, initial_I, grid1,
                                          spline_w1, base_w1, grid2,
                                          spline_w2, base_w2, gamma_p, out);
}